// round 14
// baseline (speedup 1.0000x reference)
#include <cuda_runtime.h>

// Problem constants (fixed by the dataset)
#define Nn  64      // waveguides
#define Dd  8       // decomp
#define Ww  128     // wavelengths
#define Bb  512     // batch
#define Kk  64      // chain depth
#define SEx 65      // exchange row stride in u64t (conflict-free phases)

// Smem layout (bytes):
//  phase A: ExRe0[16640] ExIm0[16640] ExRe1[16640] ExIm1[16640] | tS 32768
//           = 66560 + 32768 = 99328
//  phase B: Xr[16384] Xi[16384] at 0 | planes Mre/Mim 33792 at 66560
#define SMEM_BYTES 100352

typedef unsigned long long u64t;

// ---------------------------------------------------------------------------
__device__ __forceinline__ float gldf(const float* __restrict__ p,
                                      long long i, long long n)
{
    return (p && i >= 0 && i < n) ? p[i] : 0.0f;
}

__device__ __forceinline__ void safe_sincos(float a, float* s, float* c)
{
    float n = rintf(a * 0.15915494309189535f);
    float r = fmaf(n, -6.2831855f, a);
    r = fmaf(n, 1.7484556e-7f, r);
    sincosf(r, s, c);
}

// ---- packed f32x2 primitives ----------------------------------------------
__device__ __forceinline__ u64t pk2(float x, float y)
{ u64t r; asm("mov.b64 %0, {%1, %2};" : "=l"(r) : "f"(x), "f"(y)); return r; }

__device__ __forceinline__ void up2(u64t a, float& x, float& y)
{ asm("mov.b64 {%0, %1}, %2;" : "=f"(x), "=f"(y) : "l"(a)); }

__device__ __forceinline__ u64t padd(u64t a, u64t b)
{ u64t r; asm("add.rn.f32x2 %0, %1, %2;" : "=l"(r) : "l"(a), "l"(b)); return r; }

__device__ __forceinline__ u64t pfma(u64t a, u64t b, u64t c)
{ u64t r; asm("fma.rn.f32x2 %0, %1, %2, %3;" : "=l"(r)
              : "l"(a), "l"(b), "l"(c)); return r; }

__device__ __forceinline__ void ffma2(u64t& acc, u64t a, u64t b)
{ asm("fma.rn.f32x2 %0, %1, %2, %0;" : "+l"(acc) : "l"(a), "l"(b)); }

#define PZ 0ull

// Packed complex mul, bit-identical per lane to scalar cmul:
//   t1 = ay*wy; re = fma(ax,wx,-t1); t2 = ay*wx; im = fma(ax,wy,t2)
__device__ __forceinline__ void pcmul(u64t zr, u64t zi, u64t wxx, u64t wyy,
                                      u64t NEG1, u64t& orr, u64t& oii)
{
    u64t t1  = pfma(zi, wyy, PZ);
    u64t t1n = pfma(t1, NEG1, PZ);
    orr = pfma(zr, wxx, t1n);
    u64t t2  = pfma(zi, wxx, PZ);
    oii = pfma(zr, wyy, t2);
}

// Packed radix-4 DIF butterfly on SoA complex (re/im planes), 2 rows/lane.
__device__ __forceinline__ void bfly4p(
    u64t ar, u64t ai, u64t br, u64t bi,
    u64t cr, u64t ci, u64t dr, u64t di, u64t NEG1,
    u64t& o0r, u64t& o0i, u64t& o1r, u64t& o1i,
    u64t& o2r, u64t& o2i, u64t& o3r, u64t& o3i)
{
    u64t t0r = padd(ar, cr), t0i = padd(ai, ci);
    u64t t1r = pfma(cr, NEG1, ar), t1i = pfma(ci, NEG1, ai);
    u64t t2r = padd(br, dr), t2i = padd(bi, di);
    u64t t3r = pfma(dr, NEG1, br), t3i = pfma(di, NEG1, bi);
    o0r = padd(t0r, t2r);          o0i = padd(t0i, t2i);
    o2r = pfma(t2r, NEG1, t0r);    o2i = pfma(t2i, NEG1, t0i);
    o1r = padd(t1r, t3i);          o1i = pfma(t3r, NEG1, t1i);
    o3r = pfma(t3i, NEG1, t1r);    o3i = padd(t1i, t3r);
}

// ---------------------------------------------------------------------------
__global__ void pic_probe(float* __restrict__ outf, long long n)
{
    long long i = (long long)blockIdx.x * blockDim.x + threadIdx.x;
    if (i < n) outf[i] = 0.0f;
}

// ---------------------------------------------------------------------------
// One CTA per (d,w), 128 threads: q = tid>>5 (0..3), rp = tid&31.
// Thread holds rows {rp, rp+32} SoA-packed in lanes: X_re/X_im[16] u64t,
// element n = q+4e. Same FFT stage algebra as R12/R13 (validated), packed.
// ---------------------------------------------------------------------------
__global__ void __launch_bounds__(128)
pic_fused(const float* __restrict__ vals, long long nv,
          const float* __restrict__ wls,  long long nw,
          const float* __restrict__ xr,   long long nxr,
          const float* __restrict__ xi,   long long nxi,
          int xstride,
          float*       __restrict__ outf, long long nof)
{
    extern __shared__ char shraw[];
    u64t*   ExRe0 = (u64t*)shraw;                    // [32*SEx]
    u64t*   ExIm0 = ExRe0 + 32 * SEx;
    u64t*   ExRe1 = ExIm0 + 32 * SEx;
    u64t*   ExIm1 = ExRe1 + 32 * SEx;
    float2* tS_all = (float2*)(shraw + 66560);       // [4096]

    const int w   = blockIdx.x;
    const int d   = blockIdx.y;
    const int tid = threadIdx.x;
    const int q   = tid >> 5;               // 0..3
    const int rp  = tid & 31;               // row pair: rows rp, rp+32
    const float wl = gldf(wls, w, nw);
    const u64t NEG1 = pk2(-1.0f, -1.0f);

    // ---- Precompute 0.125*t_k[n] for all (k,n) ---------------------------
    for (int idx = tid; idx < Kk * Nn; idx += 128) {
        int k = idx >> 6, n = idx & 63;
        float Ln  = __fmul_rn(31.415926535897931f,
                    __fadd_rn(1.0f, __fmul_rn(0.01f, (float)n)));
        float v   = gldf(vals, (long long)(k * Dd + d) * Nn + n, nv);
        float phi = __fadd_rn(
            __fmul_rn(15.079644737231007f, __fdiv_rn(Ln, wl)),
            __fmul_rn(6.2831853071795862f, v));
        float s0, c0;
        safe_sincos(phi, &s0, &c0);
        float nr = __fsub_rn(0.95f, __fmul_rn(0.99f, c0));
        float ni = -__fmul_rn(0.99f, s0);
        float dr = __fsub_rn(1.0f, __fmul_rn(0.9405f, c0));
        float di = -__fmul_rn(0.9405f, s0);
        float inv = 1.0f / (dr * dr + di * di);
        tS_all[idx] = make_float2(0.125f * ((nr * dr + ni * di) * inv),
                                  0.125f * ((ni * dr - nr * di) * inv));
    }

    // ---- Twiddles (packed broadcast pairs, per-thread constants) ---------
    const float CANG = -0.09817477042468103f;   // fl(-2*pi/64)
    u64t wAx[4][3], wAy[4][3], wBx[3], wBy[3];
    #pragma unroll
    for (int e0 = 0; e0 < 4; e0++)
        #pragma unroll
        for (int r = 1; r <= 3; r++) {
            float s0, c0;
            safe_sincos(CANG * (float)((q + 4 * e0) * r), &s0, &c0);
            wAx[e0][r - 1] = pk2(c0, c0);
            wAy[e0][r - 1] = pk2(s0, s0);
        }
    #pragma unroll
    for (int s1 = 1; s1 <= 3; s1++) {
        float s0, c0;
        safe_sincos(CANG * (float)(4 * q * s1), &s0, &c0);
        wBx[s1 - 1] = pk2(c0, c0);
        wBy[s1 - 1] = pk2(s0, s0);
    }

    // M = Identity (lanes: rowA=rp, rowB=rp+32), element n = q+4e
    u64t Xre[16], Xim[16];
    #pragma unroll
    for (int e = 0; e < 16; e++) {
        int n = q + 4 * e;
        Xre[e] = pk2((n == rp) ? 1.0f : 0.0f, (n == rp + 32) ? 1.0f : 0.0f);
        Xim[e] = PZ;
    }

    __syncthreads();    // tS_all ready

    // =================== Phase A: build (64 k-steps) ======================
    for (int k = 0; k < Kk; ++k) {
        u64t* ExRe = (k & 1) ? ExRe1 : ExRe0;
        u64t* ExIm = (k & 1) ? ExIm1 : ExIm0;
        const float2* tSb = tS_all + k * Nn;

        // -------- Stage A (stride 16), thread-local ----------------------
        u64t Yre[16], Yim[16];
        #pragma unroll
        for (int e0 = 0; e0 < 4; e0++) {
            u64t o0r,o0i,o1r,o1i,o2r,o2i,o3r,o3i;
            bfly4p(Xre[e0],Xim[e0], Xre[e0+4],Xim[e0+4],
                   Xre[e0+8],Xim[e0+8], Xre[e0+12],Xim[e0+12], NEG1,
                   o0r,o0i,o1r,o1i,o2r,o2i,o3r,o3i);
            Yre[e0] = o0r; Yim[e0] = o0i;
            pcmul(o1r,o1i, wAx[e0][0],wAy[e0][0], NEG1, Yre[4+e0],  Yim[4+e0]);
            pcmul(o2r,o2i, wAx[e0][1],wAy[e0][1], NEG1, Yre[8+e0],  Yim[8+e0]);
            pcmul(o3r,o3i, wAx[e0][2],wAy[e0][2], NEG1, Yre[12+e0], Yim[12+e0]);
        }

        // -------- Stage B (stride 4) -> Ex planes ------------------------
        // slot = 16s + 4r + q  (same algebra as R12/R13)
        #pragma unroll
        for (int r = 0; r < 4; r++) {
            u64t o0r,o0i,o1r,o1i,o2r,o2i,o3r,o3i;
            bfly4p(Yre[4*r],Yim[4*r], Yre[4*r+1],Yim[4*r+1],
                   Yre[4*r+2],Yim[4*r+2], Yre[4*r+3],Yim[4*r+3], NEG1,
                   o0r,o0i,o1r,o1i,o2r,o2i,o3r,o3i);
            int base = rp * SEx + 4 * r + q;
            ExRe[base]      = o0r;  ExIm[base]      = o0i;
            u64t rr, ii;
            pcmul(o1r,o1i, wBx[0],wBy[0], NEG1, rr, ii);
            ExRe[base + 16] = rr;   ExIm[base + 16] = ii;
            pcmul(o2r,o2i, wBx[1],wBy[1], NEG1, rr, ii);
            ExRe[base + 32] = rr;   ExIm[base + 32] = ii;
            pcmul(o3r,o3i, wBx[2],wBy[2], NEG1, rr, ii);
            ExRe[base + 48] = rr;   ExIm[base + 48] = ii;
        }
        __syncthreads();

        // -------- Stage C (stride 1, r=q) + diag(t) -> back to X ---------
        #pragma unroll
        for (int s = 0; s < 4; s++) {
            int base = rp * SEx + 16 * s + 4 * q;
            u64t ar = ExRe[base+0], ai = ExIm[base+0];
            u64t br = ExRe[base+1], bi = ExIm[base+1];
            u64t cr = ExRe[base+2], ci = ExIm[base+2];
            u64t dr2 = ExRe[base+3], di2 = ExIm[base+3];
            u64t o0r,o0i,o1r,o1i,o2r,o2i,o3r,o3i;
            bfly4p(ar,ai,br,bi,cr,ci,dr2,di2, NEG1,
                   o0r,o0i,o1r,o1i,o2r,o2i,o3r,o3i);
            int nb = 4 * s + q;
            float2 t0 = tSb[nb],      t1 = tSb[nb + 16];
            float2 t2 = tSb[nb + 32], t3 = tSb[nb + 48];
            pcmul(o0r,o0i, pk2(t0.x,t0.x), pk2(t0.y,t0.y), NEG1, Xre[s],    Xim[s]);
            pcmul(o1r,o1i, pk2(t1.x,t1.x), pk2(t1.y,t1.y), NEG1, Xre[4+s],  Xim[4+s]);
            pcmul(o2r,o2i, pk2(t2.x,t2.x), pk2(t2.y,t2.y), NEG1, Xre[8+s],  Xim[8+s]);
            pcmul(o3r,o3i, pk2(t3.x,t3.x), pk2(t3.y,t3.y), NEG1, Xre[12+s], Xim[12+s]);
        }
        // no trailing sync: Ex double-buffered, tS read-only
    }
    __syncthreads();

    // ============ M -> SoA planes (Mre, -Mim), stride 66 floats ===========
    float* shf = (float*)shraw;
    float* Xr  = shf;                        // [4096] over Ex region
    float* Xi  = shf + 4096;                 // [4096]
    float* Mre = shf + 16640;                // byte ofs 66560, 4224 floats
    float* Mim = Mre + Nn * 66;              // 4224 floats (pre-negated)

    #pragma unroll
    for (int e = 0; e < 16; e++) {
        int n = q + 4 * e;
        float xa, xb, ya, yb;
        up2(Xre[e], xa, xb);
        up2(Xim[e], ya, yb);
        Mre[rp * 66 + n]        =  xa;
        Mre[(rp + 32) * 66 + n] =  xb;
        Mim[rp * 66 + n]        = -ya;
        Mim[(rp + 32) * 66 + n] = -yb;
    }
    __syncthreads();

    // =================== Phase B: apply (real part only) ==================
    const int tb = tid >> 4;            // 0..7 -> batch rows {8tb..8tb+7}
    const int ti = tid & 15;            // output cols {ti,+16,+32,+48}

    for (int bt = 0; bt < Bb / 64; ++bt) {
        for (int idx = tid; idx < 64 * Nn; idx += 128) {
            int r = idx >> 6, j = idx & 63;
            long long b = (long long)bt * 64 + r;
            long long g = ((b * Dd + d) * Ww + w) * Nn + j;
            Xr[r * 64 + j] = gldf(xr, g * xstride, nxr);
            Xi[r * 64 + j] = gldf(xi, g * xstride, nxi);
        }
        __syncthreads();

        u64t acc[8][4];
        #pragma unroll
        for (int r = 0; r < 8; r++)
            #pragma unroll
            for (int c = 0; c < 4; c++)
                acc[r][c] = 0ull;

        for (int jp = 0; jp < Nn / 2; ++jp) {
            u64t mr2[4], mi2[4];
            #pragma unroll
            for (int c = 0; c < 4; c++) {
                mr2[c] = *(const u64t*)(Mre + (ti + 16 * c) * 66 + 2 * jp);
                mi2[c] = *(const u64t*)(Mim + (ti + 16 * c) * 66 + 2 * jp);
            }
            #pragma unroll
            for (int r = 0; r < 8; r++) {
                u64t xr2 = *(const u64t*)(Xr + (tb * 8 + r) * 64 + 2 * jp);
                u64t xi2 = *(const u64t*)(Xi + (tb * 8 + r) * 64 + 2 * jp);
                #pragma unroll
                for (int c = 0; c < 4; c++) {
                    ffma2(acc[r][c], xr2, mr2[c]);
                    ffma2(acc[r][c], xi2, mi2[c]);   // Mim pre-negated
                }
            }
        }

        #pragma unroll
        for (int r = 0; r < 8; r++)
            #pragma unroll
            for (int c = 0; c < 4; c++) {
                float lo, hi;
                up2(acc[r][c], lo, hi);
                float re = lo + hi;
                long long b = (long long)bt * 64 + tb * 8 + r;
                int i = ti + 16 * c;
                long long g = ((b * Dd + d) * Ww + w) * Nn + i;
                if (g < nof) outf[g] = re;
            }
        __syncthreads();
    }
}

// ---------------------------------------------------------------------------
extern "C" void kernel_launch(void* const* d_in, const int* in_sizes, int n_in,
                              void* d_out, int out_size)
{
    const long long NX = (long long)Bb * Dd * Ww * Nn;   // 33,554,432
    const long long NV = (long long)Kk * Dd * Nn;        // 32,768
    const long long NW = Ww;                             // 128

    const float *x0 = 0, *x1 = 0, *vals = 0, *wls = 0;
    long long nx0 = 0, nx1 = 0, nv = 0, nw = 0;
    int xcomplex = 0;

    for (int pass = 0; pass < 2; ++pass) {
        long long mul = (pass == 0) ? 1 : 4;
        x0 = x1 = vals = wls = 0; nx0 = nx1 = nv = nw = 0; xcomplex = 0;
        int nxbuf = 0;
        for (int i = 0; i < n_in; i++) {
            long long s = (long long)in_sizes[i];
            const float* p = (const float*)d_in[i];
            if (!p) continue;
            if (s == NX * mul) {
                if (nxbuf == 0) { x0 = p; nx0 = NX; nxbuf = 1; }
                else if (nxbuf == 1) { x1 = p; nx1 = NX; nxbuf = 2; }
            } else if (s == 2 * NX * mul) {
                x0 = p; nx0 = 2 * NX; nxbuf = 2; xcomplex = 1;
            } else if (s == NV * mul) { if (!vals) { vals = p; nv = NV; } }
            else if (s == NW * mul)   { if (!wls)  { wls  = p; nw = NW; } }
        }
        if (nxbuf == 1 && vals && wls) {
            xcomplex = 1; nx0 = 2 * NX; x1 = 0; nxbuf = 2;
        }
        if (nxbuf == 2 && vals && wls) break;
        x0 = 0;
    }

    if (!(x0 && vals && wls) || !d_out) {
        long long n = (out_size > 4) ? (long long)out_size / 4 : 1;
        pic_probe<<<(unsigned)((n + 255) / 256), 256>>>((float*)d_out, n);
        return;
    }

    // d_out = out_size float32 (real part) — established R8.
    long long n_floats = ((long long)out_size < NX) ? (long long)out_size : NX;

    const float* xrp; const float* xip; long long nxr, nxi; int xstride;
    if (xcomplex) { xrp = x0; nxr = nx0; xip = x0 + 1; nxi = nx0 - 1; xstride = 2; }
    else          { xrp = x0; nxr = nx0; xip = x1;     nxi = nx1;     xstride = 1; }

    cudaFuncSetAttribute(pic_fused, cudaFuncAttributeMaxDynamicSharedMemorySize,
                         SMEM_BYTES);

    dim3 grid(Ww, Dd);
    pic_fused<<<grid, 128, SMEM_BYTES>>>(vals, nv, wls, nw,
                                         xrp, nxr, xip, nxi, xstride,
                                         (float*)d_out, n_floats);
}

// round 15
// speedup vs baseline: 1.1528x; 1.1528x over previous
#include <cuda_runtime.h>

// Problem constants (fixed by the dataset)
#define Nn  64      // waveguides
#define Dd  8       // decomp
#define Ww  128     // wavelengths
#define Bb  512     // batch
#define Kk  64      // chain depth

// Smem layout (bytes):
//  phase A: tS_all [0, 32768)
//  phase B: Xr [0,32768) Xi [32768,65536) | planes Mre/Mim at 66560 (33792)
#define SMEM_BYTES 100352

typedef unsigned long long u64t;

// ---------------------------------------------------------------------------
__device__ __forceinline__ float gldf(const float* __restrict__ p,
                                      long long i, long long n)
{
    return (p && i >= 0 && i < n) ? p[i] : 0.0f;
}

__device__ __forceinline__ void safe_sincos(float a, float* s, float* c)
{
    float n = rintf(a * 0.15915494309189535f);
    float r = fmaf(n, -6.2831855f, a);
    r = fmaf(n, 1.7484556e-7f, r);
    sincosf(r, s, c);
}

__device__ __forceinline__ float2 cmul(float2 a, float2 b)
{
    return make_float2(fmaf(a.x, b.x, -a.y * b.y),
                       fmaf(a.x, b.y,  a.y * b.x));
}

// Packed dual-lane FMA for the APPLY phase only (R10/R12/R13-validated)
__device__ __forceinline__ void ffma2(u64t& acc, u64t a, u64t b)
{ asm("fma.rn.f32x2 %0, %1, %2, %0;" : "+l"(acc) : "l"(a), "l"(b)); }

// Radix-4 DIF butterfly (plain float2 — validated codegen)
__device__ __forceinline__ void bfly4(float2 a, float2 b, float2 c, float2 d,
                                      float2& o0, float2& o1,
                                      float2& o2, float2& o3)
{
    float t0x = a.x + c.x, t0y = a.y + c.y;
    float t1x = a.x - c.x, t1y = a.y - c.y;
    float t2x = b.x + d.x, t2y = b.y + d.y;
    float t3x = b.x - d.x, t3y = b.y - d.y;
    o0 = make_float2(t0x + t2x, t0y + t2y);
    o2 = make_float2(t0x - t2x, t0y - t2y);
    o1 = make_float2(t1x + t3y, t1y - t3x);
    o3 = make_float2(t1x - t3y, t1y + t3x);
}

__device__ __forceinline__ float2 shflx2(float2 v, int m)
{
    v.x = __shfl_xor_sync(0xffffffffu, v.x, m);
    v.y = __shfl_xor_sync(0xffffffffu, v.y, m);
    return v;
}

// ---------------------------------------------------------------------------
__global__ void pic_probe(float* __restrict__ outf, long long n)
{
    long long i = (long long)blockIdx.x * blockDim.x + threadIdx.x;
    if (i < n) outf[i] = 0.0f;
}

// ---------------------------------------------------------------------------
// One CTA per (d,w), 256 threads: q = tid&3, row = tid>>2.
// The 4 threads of a row are ADJACENT LANES -> stage-B/C exchange is an
// in-warp 4x4 butterfly transpose (shfl_xor 1 then 2). ZERO syncthreads and
// ZERO smem traffic in the 64-step k-loop; warps fully independent.
// Stage algebra identical to R12/R13 (validated): thread holds
// X[e] = M[row, q+4e]; stage C (r=q) returns outputs to its own X.
// ---------------------------------------------------------------------------
__global__ void __launch_bounds__(256, 2)
pic_fused(const float* __restrict__ vals, long long nv,
          const float* __restrict__ wls,  long long nw,
          const float* __restrict__ xr,   long long nxr,
          const float* __restrict__ xi,   long long nxi,
          int xstride,
          float*       __restrict__ outf, long long nof)
{
    extern __shared__ char shraw[];
    float2* tS_all = (float2*)shraw;        // [4096] (phase A only)

    const int w   = blockIdx.x;
    const int d   = blockIdx.y;
    const int tid = threadIdx.x;
    const int q   = tid & 3;                // 0..3 (lane-group position)
    const int row = tid >> 2;               // 0..63
    const float wl = gldf(wls, w, nw);

    // ---- Precompute 0.125*t_k[n] for all (k,n) ---------------------------
    for (int idx = tid; idx < Kk * Nn; idx += 256) {
        int k = idx >> 6, n = idx & 63;
        float Ln  = __fmul_rn(31.415926535897931f,
                    __fadd_rn(1.0f, __fmul_rn(0.01f, (float)n)));
        float v   = gldf(vals, (long long)(k * Dd + d) * Nn + n, nv);
        float phi = __fadd_rn(
            __fmul_rn(15.079644737231007f, __fdiv_rn(Ln, wl)),
            __fmul_rn(6.2831853071795862f, v));
        float s0, c0;
        safe_sincos(phi, &s0, &c0);
        float nr = __fsub_rn(0.95f, __fmul_rn(0.99f, c0));
        float ni = -__fmul_rn(0.99f, s0);
        float dr = __fsub_rn(1.0f, __fmul_rn(0.9405f, c0));
        float di = -__fmul_rn(0.9405f, s0);
        float inv = 1.0f / (dr * dr + di * di);
        tS_all[idx] = make_float2(0.125f * ((nr * dr + ni * di) * inv),
                                  0.125f * ((ni * dr - nr * di) * inv));
    }

    // Twiddles (per-thread constants, reference-matching f32 angles)
    const float CANG = -0.09817477042468103f;   // fl(-2*pi/64)
    float2 wA[4][3], wB[3];
    #pragma unroll
    for (int e0 = 0; e0 < 4; e0++)
        #pragma unroll
        for (int r = 1; r <= 3; r++) {
            float s0, c0;
            safe_sincos(CANG * (float)((q + 4 * e0) * r), &s0, &c0);
            wA[e0][r - 1] = make_float2(c0, s0);
        }
    #pragma unroll
    for (int s1 = 1; s1 <= 3; s1++) {
        float s0, c0;
        safe_sincos(CANG * (float)(4 * q * s1), &s0, &c0);
        wB[s1 - 1] = make_float2(c0, s0);
    }

    // M = Identity, register-resident: X[e] = M[row, q+4e]
    float2 X[16];
    #pragma unroll
    for (int e = 0; e < 16; e++)
        X[e] = make_float2((q + 4 * e == row) ? 1.0f : 0.0f, 0.0f);

    __syncthreads();    // tS_all ready (only sync before the k-loop)

    // =================== Phase A: build (64 k-steps, sync-free) ===========
    for (int k = 0; k < Kk; ++k) {
        const float2* tSb = tS_all + k * Nn;

        // -------- Stage A (stride 16), thread-local ----------------------
        float2 Y[16];
        #pragma unroll
        for (int e0 = 0; e0 < 4; e0++) {
            float2 o0, o1, o2, o3;
            bfly4(X[e0], X[e0 + 4], X[e0 + 8], X[e0 + 12], o0, o1, o2, o3);
            Y[e0]      = o0;
            Y[4 + e0]  = cmul(o1, wA[e0][0]);
            Y[8 + e0]  = cmul(o2, wA[e0][1]);
            Y[12 + e0] = cmul(o3, wA[e0][2]);
        }

        // -------- Stage B (stride 4): V[r][s] = z_{r,s}[u=q] -------------
        float2 V[4][4];
        #pragma unroll
        for (int r = 0; r < 4; r++) {
            float2 o0, o1, o2, o3;
            bfly4(Y[4 * r + 0], Y[4 * r + 1], Y[4 * r + 2], Y[4 * r + 3],
                  o0, o1, o2, o3);
            V[r][0] = o0;
            V[r][1] = cmul(o1, wB[0]);
            V[r][2] = cmul(o2, wB[1]);
            V[r][3] = cmul(o3, wB[2]);
        }

        // -------- Stage C: in-warp 4x4 transpose + bfly + diag(t) --------
        #pragma unroll
        for (int s = 0; s < 4; s++) {
            float2 a0 = V[0][s], a1 = V[1][s], a2 = V[2][s], a3 = V[3][s];
            // step 1: swap lane-bit0 with element-bit0 (xor 1)
            float2 e0 = (q & 1) ? a0 : a1;
            float2 e1 = (q & 1) ? a2 : a3;
            e0 = shflx2(e0, 1);
            e1 = shflx2(e1, 1);
            if (q & 1) { a0 = e0; a2 = e1; } else { a1 = e0; a3 = e1; }
            // step 2: swap lane-bit1 with element-bit1 (xor 2)
            float2 f0 = (q & 2) ? a0 : a2;
            float2 f1 = (q & 2) ? a1 : a3;
            f0 = shflx2(f0, 2);
            f1 = shflx2(f1, 2);
            if (q & 2) { a0 = f0; a1 = f1; } else { a2 = f0; a3 = f1; }
            // now a_u = z_{q,s}[u]  (u = 0..3)
            float2 o0, o1, o2, o3;
            bfly4(a0, a1, a2, a3, o0, o1, o2, o3);
            int nb = 4 * s + q;
            X[s]      = cmul(o0, tSb[nb]);          // tau=0
            X[4 + s]  = cmul(o1, tSb[nb + 16]);     // tau=1
            X[8 + s]  = cmul(o2, tSb[nb + 32]);     // tau=2
            X[12 + s] = cmul(o3, tSb[nb + 48]);     // tau=3
        }
    }
    __syncthreads();   // all tS_all reads done before smem is repurposed

    // ============ M -> SoA planes (Mre, -Mim), stride 66 floats ===========
    float* shf = (float*)shraw;
    float* Xr  = shf;                       // [8192] floats (128x64)
    float* Xi  = shf + 8192;                // [8192] floats
    float* Mre = shf + 16640;               // byte ofs 66560, 4224 floats
    float* Mim = Mre + Nn * 66;             // 4224 floats (pre-negated)

    #pragma unroll
    for (int e = 0; e < 16; e++) {
        int n = q + 4 * e;
        Mre[row * 66 + n] =  X[e].x;
        Mim[row * 66 + n] = -X[e].y;
    }
    __syncthreads();

    // =================== Phase B: apply (real part only) ==================
    const int tb = tid >> 4;            // 0..15 -> batch rows {8tb..8tb+7}
    const int ti = tid & 15;            // output cols {ti,+16,+32,+48}

    for (int bt = 0; bt < Bb / 128; ++bt) {
        for (int idx = tid; idx < 128 * Nn; idx += 256) {
            int r = idx >> 6, j = idx & 63;
            long long b = (long long)bt * 128 + r;
            long long g = ((b * Dd + d) * Ww + w) * Nn + j;
            Xr[r * 64 + j] = gldf(xr, g * xstride, nxr);
            Xi[r * 64 + j] = gldf(xi, g * xstride, nxi);
        }
        __syncthreads();

        u64t acc[8][4];
        #pragma unroll
        for (int r = 0; r < 8; r++)
            #pragma unroll
            for (int c = 0; c < 4; c++)
                acc[r][c] = 0ull;

        for (int jp = 0; jp < Nn / 2; ++jp) {
            u64t mr2[4], mi2[4];
            #pragma unroll
            for (int c = 0; c < 4; c++) {
                mr2[c] = *(const u64t*)(Mre + (ti + 16 * c) * 66 + 2 * jp);
                mi2[c] = *(const u64t*)(Mim + (ti + 16 * c) * 66 + 2 * jp);
            }
            #pragma unroll
            for (int r = 0; r < 8; r++) {
                u64t xr2 = *(const u64t*)(Xr + (tb * 8 + r) * 64 + 2 * jp);
                u64t xi2 = *(const u64t*)(Xi + (tb * 8 + r) * 64 + 2 * jp);
                #pragma unroll
                for (int c = 0; c < 4; c++) {
                    ffma2(acc[r][c], xr2, mr2[c]);
                    ffma2(acc[r][c], xi2, mi2[c]);   // Mim pre-negated
                }
            }
        }

        #pragma unroll
        for (int r = 0; r < 8; r++)
            #pragma unroll
            for (int c = 0; c < 4; c++) {
                float lo = __uint_as_float((unsigned)(acc[r][c] & 0xffffffffu));
                float hi = __uint_as_float((unsigned)(acc[r][c] >> 32));
                float re = lo + hi;
                long long b = (long long)bt * 128 + tb * 8 + r;
                int i = ti + 16 * c;
                long long g = ((b * Dd + d) * Ww + w) * Nn + i;
                if (g < nof) outf[g] = re;
            }
        __syncthreads();
    }
}

// ---------------------------------------------------------------------------
extern "C" void kernel_launch(void* const* d_in, const int* in_sizes, int n_in,
                              void* d_out, int out_size)
{
    const long long NX = (long long)Bb * Dd * Ww * Nn;   // 33,554,432
    const long long NV = (long long)Kk * Dd * Nn;        // 32,768
    const long long NW = Ww;                             // 128

    const float *x0 = 0, *x1 = 0, *vals = 0, *wls = 0;
    long long nx0 = 0, nx1 = 0, nv = 0, nw = 0;
    int xcomplex = 0;

    for (int pass = 0; pass < 2; ++pass) {
        long long mul = (pass == 0) ? 1 : 4;
        x0 = x1 = vals = wls = 0; nx0 = nx1 = nv = nw = 0; xcomplex = 0;
        int nxbuf = 0;
        for (int i = 0; i < n_in; i++) {
            long long s = (long long)in_sizes[i];
            const float* p = (const float*)d_in[i];
            if (!p) continue;
            if (s == NX * mul) {
                if (nxbuf == 0) { x0 = p; nx0 = NX; nxbuf = 1; }
                else if (nxbuf == 1) { x1 = p; nx1 = NX; nxbuf = 2; }
            } else if (s == 2 * NX * mul) {
                x0 = p; nx0 = 2 * NX; nxbuf = 2; xcomplex = 1;
            } else if (s == NV * mul) { if (!vals) { vals = p; nv = NV; } }
            else if (s == NW * mul)   { if (!wls)  { wls  = p; nw = NW; } }
        }
        if (nxbuf == 1 && vals && wls) {
            xcomplex = 1; nx0 = 2 * NX; x1 = 0; nxbuf = 2;
        }
        if (nxbuf == 2 && vals && wls) break;
        x0 = 0;
    }

    if (!(x0 && vals && wls) || !d_out) {
        long long n = (out_size > 4) ? (long long)out_size / 4 : 1;
        pic_probe<<<(unsigned)((n + 255) / 256), 256>>>((float*)d_out, n);
        return;
    }

    // d_out = out_size float32 (real part) — established R8.
    long long n_floats = ((long long)out_size < NX) ? (long long)out_size : NX;

    const float* xrp; const float* xip; long long nxr, nxi; int xstride;
    if (xcomplex) { xrp = x0; nxr = nx0; xip = x0 + 1; nxi = nx0 - 1; xstride = 2; }
    else          { xrp = x0; nxr = nx0; xip = x1;     nxi = nx1;     xstride = 1; }

    cudaFuncSetAttribute(pic_fused, cudaFuncAttributeMaxDynamicSharedMemorySize,
                         SMEM_BYTES);

    dim3 grid(Ww, Dd);
    pic_fused<<<grid, 256, SMEM_BYTES>>>(vals, nv, wls, nw,
                                         xrp, nxr, xip, nxi, xstride,
                                         (float*)d_out, n_floats);
}

// round 16
// speedup vs baseline: 1.1643x; 1.0100x over previous
#include <cuda_runtime.h>

// Problem constants (fixed by the dataset)
#define Nn  64      // waveguides
#define Dd  8       // decomp
#define Ww  128     // wavelengths
#define Bb  512     // batch
#define Kk  64      // chain depth
#define Sd  65      // Ex row stride (float2): conflict-free 16-lane phases

// Smem layout (float2 units):
//   phase A: ExA [0,4160) + ExB [4160,8320) + tS_all [8320,12416)
//   phase B: Xr/Xi [0,8192) (128x64 floats each) + planes [8320,12544)
#define SMEM_F2    12544
#define SMEM_BYTES (SMEM_F2 * (int)sizeof(float2))   // 100352 B

typedef unsigned long long u64t;

// ---------------------------------------------------------------------------
__device__ __forceinline__ float gldf(const float* __restrict__ p,
                                      long long i, long long n)
{
    return (p && i >= 0 && i < n) ? p[i] : 0.0f;
}

__device__ __forceinline__ void safe_sincos(float a, float* s, float* c)
{
    float n = rintf(a * 0.15915494309189535f);
    float r = fmaf(n, -6.2831855f, a);
    r = fmaf(n, 1.7484556e-7f, r);
    sincosf(r, s, c);
}

__device__ __forceinline__ float2 cmul(float2 a, float2 b)
{
    return make_float2(fmaf(a.x, b.x, -a.y * b.y),
                       fmaf(a.x, b.y,  a.y * b.x));
}

// FFMA-imm add/sub: bit-identical to a+b / a-b (x*±1.0 exact, one rounding),
// but SASS FFMA with immediate multiplier has rt_SMSP=1 vs FADD's 2.
__device__ __forceinline__ float faddx(float a, float b)
{ float r; asm("fma.rn.f32 %0, %1, 0f3F800000, %2;"
               : "=f"(r) : "f"(a), "f"(b)); return r; }
__device__ __forceinline__ float fsubx(float a, float b)   // a - b
{ float r; asm("fma.rn.f32 %0, %1, 0fBF800000, %2;"
               : "=f"(r) : "f"(b), "f"(a)); return r; }

// Packed dual-lane FMA for the APPLY phase only (validated in R10/R12/R13)
__device__ __forceinline__ void ffma2(u64t& acc, u64t a, u64t b)
{ asm("fma.rn.f32x2 %0, %1, %2, %0;" : "+l"(acc) : "l"(a), "l"(b)); }

// Radix-4 DIF butterfly — adds/subs via FFMA-imm (bit-identical results)
__device__ __forceinline__ void bfly4(float2 a, float2 b, float2 c, float2 d,
                                      float2& o0, float2& o1,
                                      float2& o2, float2& o3)
{
    float t0x = faddx(a.x, c.x), t0y = faddx(a.y, c.y);
    float t1x = fsubx(a.x, c.x), t1y = fsubx(a.y, c.y);
    float t2x = faddx(b.x, d.x), t2y = faddx(b.y, d.y);
    float t3x = fsubx(b.x, d.x), t3y = fsubx(b.y, d.y);
    o0 = make_float2(faddx(t0x, t2x), faddx(t0y, t2y));
    o2 = make_float2(fsubx(t0x, t2x), fsubx(t0y, t2y));
    o1 = make_float2(faddx(t1x, t3y), fsubx(t1y, t3x));
    o3 = make_float2(fsubx(t1x, t3y), faddx(t1y, t3x));
}

// ---------------------------------------------------------------------------
__global__ void pic_probe(float* __restrict__ outf, long long n)
{
    long long i = (long long)blockIdx.x * blockDim.x + threadIdx.x;
    if (i < n) outf[i] = 0.0f;
}

// ---------------------------------------------------------------------------
// One CTA per (d,w), 256 threads.  (R13 structure, validated 513.5us)
// Phase A: thread (q=tid>>6,row=tid&63) holds X[e]=M[row,q+4e] in registers
// across 64 k-steps; one double-buffered smem exchange + one sync per k.
// t for ALL k precomputed once into tS_all (warp-broadcast reads in stage C).
// Phase B: real-part apply, 8b x 4i register tile, 128-row batch tiles.
// ---------------------------------------------------------------------------
__global__ void __launch_bounds__(256, 2)
pic_fused(const float* __restrict__ vals, long long nv,
          const float* __restrict__ wls,  long long nw,
          const float* __restrict__ xr,   long long nxr,
          const float* __restrict__ xi,   long long nxi,
          int xstride,
          float*       __restrict__ outf, long long nof)
{
    extern __shared__ float2 sh[];
    float2* ExA    = sh;                    // [4160)
    float2* ExB    = sh + Nn * Sd;          // [4160)
    float2* tS_all = sh + 2 * Nn * Sd;      // [4096): tS_all[k*64+n]

    const int w   = blockIdx.x;
    const int d   = blockIdx.y;
    const int tid = threadIdx.x;
    const int q   = tid >> 6;               // 0..3
    const int row = tid & 63;
    const float wl = gldf(wls, w, nw);

    // ---- Precompute 0.125*t_k[n] for ALL (k,n) ---------------------------
    for (int idx = tid; idx < Kk * Nn; idx += 256) {
        int k = idx >> 6, n = idx & 63;
        float Ln  = __fmul_rn(31.415926535897931f,
                    __fadd_rn(1.0f, __fmul_rn(0.01f, (float)n)));
        float v   = gldf(vals, (long long)(k * Dd + d) * Nn + n, nv);
        float phi = __fadd_rn(
            __fmul_rn(15.079644737231007f, __fdiv_rn(Ln, wl)),
            __fmul_rn(6.2831853071795862f, v));
        float s0, c0;
        safe_sincos(phi, &s0, &c0);
        float nr = __fsub_rn(0.95f, __fmul_rn(0.99f, c0));
        float ni = -__fmul_rn(0.99f, s0);
        float dr = __fsub_rn(1.0f, __fmul_rn(0.9405f, c0));
        float di = -__fmul_rn(0.9405f, s0);
        float inv = 1.0f / (dr * dr + di * di);
        tS_all[idx] = make_float2(0.125f * ((nr * dr + ni * di) * inv),
                                  0.125f * ((ni * dr - nr * di) * inv));
    }

    // Twiddles (per-thread constants, reference-matching f32 angles)
    const float CANG = -0.09817477042468103f;   // fl(-2*pi/64)
    float2 wA[4][3], wB[3];
    #pragma unroll
    for (int e0 = 0; e0 < 4; e0++)
        #pragma unroll
        for (int r = 1; r <= 3; r++) {
            float s0, c0;
            safe_sincos(CANG * (float)((q + 4 * e0) * r), &s0, &c0);
            wA[e0][r - 1] = make_float2(c0, s0);
        }
    #pragma unroll
    for (int s1 = 1; s1 <= 3; s1++) {
        float s0, c0;
        safe_sincos(CANG * (float)(4 * q * s1), &s0, &c0);
        wB[s1 - 1] = make_float2(c0, s0);
    }

    // M = Identity, register-resident: X[e] = M[row, q+4e]
    float2 X[16];
    #pragma unroll
    for (int e = 0; e < 16; e++)
        X[e] = make_float2((q + 4 * e == row) ? 1.0f : 0.0f, 0.0f);

    __syncthreads();    // tS_all visible to all

    // =================== Phase A: build (64 k-steps) ======================
    for (int k = 0; k < Kk; ++k) {
        float2* Ex = (k & 1) ? ExB : ExA;
        const float2* tSb = tS_all + k * Nn;

        // -------- Stage A (stride 16), thread-local ----------------------
        float2 Y[16];
        #pragma unroll
        for (int e0 = 0; e0 < 4; e0++) {
            float2 o0, o1, o2, o3;
            bfly4(X[e0], X[e0 + 4], X[e0 + 8], X[e0 + 12], o0, o1, o2, o3);
            Y[e0]      = o0;
            Y[4 + e0]  = cmul(o1, wA[e0][0]);
            Y[8 + e0]  = cmul(o2, wA[e0][1]);
            Y[12 + e0] = cmul(o3, wA[e0][2]);
        }

        // -------- Stage B (stride 4) -> Ex exchange ----------------------
        #pragma unroll
        for (int r = 0; r < 4; r++) {
            float2 o0, o1, o2, o3;
            bfly4(Y[4 * r + 0], Y[4 * r + 1], Y[4 * r + 2], Y[4 * r + 3],
                  o0, o1, o2, o3);
            int base = row * Sd + q;
            Ex[base + 4 * r]      = o0;                 // s=0
            Ex[base + 16 + 4 * r] = cmul(o1, wB[0]);    // s=1
            Ex[base + 32 + 4 * r] = cmul(o2, wB[1]);    // s=2
            Ex[base + 48 + 4 * r] = cmul(o3, wB[2]);    // s=3
        }
        __syncthreads();

        // -------- Stage C (stride 1, r=q) + diag(t) -> back to X ---------
        #pragma unroll
        for (int s = 0; s < 4; s++) {
            int base = row * Sd + 16 * s + 4 * q;
            float2 o0, o1, o2, o3;
            bfly4(Ex[base + 0], Ex[base + 1], Ex[base + 2], Ex[base + 3],
                  o0, o1, o2, o3);
            int nb = 4 * s + q;
            X[s]      = cmul(o0, tSb[nb]);          // tau=0
            X[4 + s]  = cmul(o1, tSb[nb + 16]);     // tau=1
            X[8 + s]  = cmul(o2, tSb[nb + 32]);     // tau=2
            X[12 + s] = cmul(o3, tSb[nb + 48]);     // tau=3
        }
        // no trailing sync: Ex double-buffered; tS_all read-only
    }
    __syncthreads();   // all stage-C reads done before smem is repurposed

    // ============ M -> SoA planes (Mre, -Mim), stride 66 floats ===========
    float* shf = (float*)sh;
    float* Xr  = shf;                       // [8192] floats (128x64)
    float* Xi  = shf + 8192;                // [8192] floats
    float* Mre = shf + 2 * (2 * Nn * Sd);   // float ofs 16640, 4224 floats
    float* Mim = Mre + Nn * 66;             // 4224 floats (pre-negated)

    #pragma unroll
    for (int e = 0; e < 16; e++) {
        int n = q + 4 * e;
        Mre[row * 66 + n] =  X[e].x;
        Mim[row * 66 + n] = -X[e].y;
    }
    __syncthreads();

    // =================== Phase B: apply (real part only) ==================
    const int tb = tid >> 4;            // 0..15 -> batch rows {8tb..8tb+7}
    const int ti = tid & 15;            // output cols {ti,+16,+32,+48}

    for (int bt = 0; bt < Bb / 128; ++bt) {
        for (int idx = tid; idx < 128 * Nn; idx += 256) {
            int r = idx >> 6, j = idx & 63;
            long long b = (long long)bt * 128 + r;
            long long g = ((b * Dd + d) * Ww + w) * Nn + j;
            Xr[r * 64 + j] = gldf(xr, g * xstride, nxr);
            Xi[r * 64 + j] = gldf(xi, g * xstride, nxi);
        }
        __syncthreads();

        u64t acc[8][4];
        #pragma unroll
        for (int r = 0; r < 8; r++)
            #pragma unroll
            for (int c = 0; c < 4; c++)
                acc[r][c] = 0ull;

        for (int jp = 0; jp < Nn / 2; ++jp) {
            u64t mr2[4], mi2[4];
            #pragma unroll
            for (int c = 0; c < 4; c++) {
                mr2[c] = *(const u64t*)(Mre + (ti + 16 * c) * 66 + 2 * jp);
                mi2[c] = *(const u64t*)(Mim + (ti + 16 * c) * 66 + 2 * jp);
            }
            #pragma unroll
            for (int r = 0; r < 8; r++) {
                u64t xr2 = *(const u64t*)(Xr + (tb * 8 + r) * 64 + 2 * jp);
                u64t xi2 = *(const u64t*)(Xi + (tb * 8 + r) * 64 + 2 * jp);
                #pragma unroll
                for (int c = 0; c < 4; c++) {
                    ffma2(acc[r][c], xr2, mr2[c]);
                    ffma2(acc[r][c], xi2, mi2[c]);   // Mim pre-negated
                }
            }
        }

        #pragma unroll
        for (int r = 0; r < 8; r++)
            #pragma unroll
            for (int c = 0; c < 4; c++) {
                float lo = __uint_as_float((unsigned)(acc[r][c] & 0xffffffffu));
                float hi = __uint_as_float((unsigned)(acc[r][c] >> 32));
                float re = lo + hi;
                long long b = (long long)bt * 128 + tb * 8 + r;
                int i = ti + 16 * c;
                long long g = ((b * Dd + d) * Ww + w) * Nn + i;
                if (g < nof) outf[g] = re;
            }
        __syncthreads();
    }
}

// ---------------------------------------------------------------------------
extern "C" void kernel_launch(void* const* d_in, const int* in_sizes, int n_in,
                              void* d_out, int out_size)
{
    const long long NX = (long long)Bb * Dd * Ww * Nn;   // 33,554,432
    const long long NV = (long long)Kk * Dd * Nn;        // 32,768
    const long long NW = Ww;                             // 128

    const float *x0 = 0, *x1 = 0, *vals = 0, *wls = 0;
    long long nx0 = 0, nx1 = 0, nv = 0, nw = 0;
    int xcomplex = 0;

    for (int pass = 0; pass < 2; ++pass) {
        long long mul = (pass == 0) ? 1 : 4;
        x0 = x1 = vals = wls = 0; nx0 = nx1 = nv = nw = 0; xcomplex = 0;
        int nxbuf = 0;
        for (int i = 0; i < n_in; i++) {
            long long s = (long long)in_sizes[i];
            const float* p = (const float*)d_in[i];
            if (!p) continue;
            if (s == NX * mul) {
                if (nxbuf == 0) { x0 = p; nx0 = NX; nxbuf = 1; }
                else if (nxbuf == 1) { x1 = p; nx1 = NX; nxbuf = 2; }
            } else if (s == 2 * NX * mul) {
                x0 = p; nx0 = 2 * NX; nxbuf = 2; xcomplex = 1;
            } else if (s == NV * mul) { if (!vals) { vals = p; nv = NV; } }
            else if (s == NW * mul)   { if (!wls)  { wls  = p; nw = NW; } }
        }
        if (nxbuf == 1 && vals && wls) {
            xcomplex = 1; nx0 = 2 * NX; x1 = 0; nxbuf = 2;
        }
        if (nxbuf == 2 && vals && wls) break;
        x0 = 0;
    }

    if (!(x0 && vals && wls) || !d_out) {
        long long n = (out_size > 4) ? (long long)out_size / 4 : 1;
        pic_probe<<<(unsigned)((n + 255) / 256), 256>>>((float*)d_out, n);
        return;
    }

    // d_out = out_size float32 (real part) — established R8.
    long long n_floats = ((long long)out_size < NX) ? (long long)out_size : NX;

    const float* xrp; const float* xip; long long nxr, nxi; int xstride;
    if (xcomplex) { xrp = x0; nxr = nx0; xip = x0 + 1; nxi = nx0 - 1; xstride = 2; }
    else          { xrp = x0; nxr = nx0; xip = x1;     nxi = nx1;     xstride = 1; }

    cudaFuncSetAttribute(pic_fused, cudaFuncAttributeMaxDynamicSharedMemorySize,
                         SMEM_BYTES);

    dim3 grid(Ww, Dd);
    pic_fused<<<grid, 256, SMEM_BYTES>>>(vals, nv, wls, nw,
                                         xrp, nxr, xip, nxi, xstride,
                                         (float*)d_out, n_floats);
}

// round 17
// speedup vs baseline: 1.1659x; 1.0014x over previous
#include <cuda_runtime.h>

// Problem constants (fixed by the dataset)
#define Nn  64      // waveguides
#define Dd  8       // decomp
#define Ww  128     // wavelengths
#define Bb  512     // batch
#define Kk  64      // chain depth
#define Sd  69      // Ex row stride (float2): bank shift 10/row -> <=2-way

// Smem layout (bytes):
//  phase A: Ex [0, 35328) + tS_all [35328, 68096)
//  phase B: Xr [0,32768) Xi [32768,65536) | planes at 68096 (33792)
#define SMEM_BYTES 101888

typedef unsigned long long u64t;

// ---------------------------------------------------------------------------
__device__ __forceinline__ float gldf(const float* __restrict__ p,
                                      long long i, long long n)
{
    return (p && i >= 0 && i < n) ? p[i] : 0.0f;
}

__device__ __forceinline__ void safe_sincos(float a, float* s, float* c)
{
    float n = rintf(a * 0.15915494309189535f);
    float r = fmaf(n, -6.2831855f, a);
    r = fmaf(n, 1.7484556e-7f, r);
    sincosf(r, s, c);
}

__device__ __forceinline__ float2 cmul(float2 a, float2 b)
{
    return make_float2(fmaf(a.x, b.x, -a.y * b.y),
                       fmaf(a.x, b.y,  a.y * b.x));
}

// Packed dual-lane FMA for the APPLY phase only (R10/R12/R13-validated)
__device__ __forceinline__ void ffma2(u64t& acc, u64t a, u64t b)
{ asm("fma.rn.f32x2 %0, %1, %2, %0;" : "+l"(acc) : "l"(a), "l"(b)); }

// Radix-4 DIF butterfly (plain float2 — R13-validated codegen)
__device__ __forceinline__ void bfly4(float2 a, float2 b, float2 c, float2 d,
                                      float2& o0, float2& o1,
                                      float2& o2, float2& o3)
{
    float t0x = a.x + c.x, t0y = a.y + c.y;
    float t1x = a.x - c.x, t1y = a.y - c.y;
    float t2x = b.x + d.x, t2y = b.y + d.y;
    float t3x = b.x - d.x, t3y = b.y - d.y;
    o0 = make_float2(t0x + t2x, t0y + t2y);
    o2 = make_float2(t0x - t2x, t0y - t2y);
    o1 = make_float2(t1x + t3y, t1y - t3x);
    o3 = make_float2(t1x - t3y, t1y + t3x);
}

// ---------------------------------------------------------------------------
__global__ void pic_probe(float* __restrict__ outf, long long n)
{
    long long i = (long long)blockIdx.x * blockDim.x + threadIdx.x;
    if (i < n) outf[i] = 0.0f;
}

// ---------------------------------------------------------------------------
// One CTA per (d,w), 256 threads: q = tid&3, row = tid>>2.
// The 4 threads of each row are ADJACENT LANES -> the stage-B/C smem
// exchange region (rows 8w..8w+7 for warp w) is WARP-PRIVATE. The per-k
// block barrier becomes two __syncwarp()s: warps free-run at independent
// phases, overlapping fma bursts with LDS bursts across warps.
// Stage algebra + arithmetic identical to R13 (validated 513.5us).
// ---------------------------------------------------------------------------
__global__ void __launch_bounds__(256, 2)
pic_fused(const float* __restrict__ vals, long long nv,
          const float* __restrict__ wls,  long long nw,
          const float* __restrict__ xr,   long long nxr,
          const float* __restrict__ xi,   long long nxi,
          int xstride,
          float*       __restrict__ outf, long long nof)
{
    extern __shared__ float2 sh[];
    float2* Ex     = sh;                    // [64*Sd]  warp-private rows
    float2* tS_all = sh + Nn * Sd;          // [4096]: tS_all[k*64+n]

    const int w   = blockIdx.x;
    const int d   = blockIdx.y;
    const int tid = threadIdx.x;
    const int q   = tid & 3;                // 0..3 (adjacent lanes per row)
    const int row = tid >> 2;               // 0..63
    const float wl = gldf(wls, w, nw);

    // ---- Precompute 0.125*t_k[n] for ALL (k,n) ---------------------------
    for (int idx = tid; idx < Kk * Nn; idx += 256) {
        int k = idx >> 6, n = idx & 63;
        float Ln  = __fmul_rn(31.415926535897931f,
                    __fadd_rn(1.0f, __fmul_rn(0.01f, (float)n)));
        float v   = gldf(vals, (long long)(k * Dd + d) * Nn + n, nv);
        float phi = __fadd_rn(
            __fmul_rn(15.079644737231007f, __fdiv_rn(Ln, wl)),
            __fmul_rn(6.2831853071795862f, v));
        float s0, c0;
        safe_sincos(phi, &s0, &c0);
        float nr = __fsub_rn(0.95f, __fmul_rn(0.99f, c0));
        float ni = -__fmul_rn(0.99f, s0);
        float dr = __fsub_rn(1.0f, __fmul_rn(0.9405f, c0));
        float di = -__fmul_rn(0.9405f, s0);
        float inv = 1.0f / (dr * dr + di * di);
        tS_all[idx] = make_float2(0.125f * ((nr * dr + ni * di) * inv),
                                  0.125f * ((ni * dr - nr * di) * inv));
    }

    // Twiddles (per-thread constants, reference-matching f32 angles)
    const float CANG = -0.09817477042468103f;   // fl(-2*pi/64)
    float2 wA[4][3], wB[3];
    #pragma unroll
    for (int e0 = 0; e0 < 4; e0++)
        #pragma unroll
        for (int r = 1; r <= 3; r++) {
            float s0, c0;
            safe_sincos(CANG * (float)((q + 4 * e0) * r), &s0, &c0);
            wA[e0][r - 1] = make_float2(c0, s0);
        }
    #pragma unroll
    for (int s1 = 1; s1 <= 3; s1++) {
        float s0, c0;
        safe_sincos(CANG * (float)(4 * q * s1), &s0, &c0);
        wB[s1 - 1] = make_float2(c0, s0);
    }

    // M = Identity, register-resident: X[e] = M[row, q+4e]
    float2 X[16];
    #pragma unroll
    for (int e = 0; e < 16; e++)
        X[e] = make_float2((q + 4 * e == row) ? 1.0f : 0.0f, 0.0f);

    __syncthreads();    // tS_all visible (only block barrier before k-loop)

    // =================== Phase A: build (64 k-steps) ======================
    for (int k = 0; k < Kk; ++k) {
        const float2* tSb = tS_all + k * Nn;

        // -------- Stage A (stride 16), thread-local ----------------------
        float2 Y[16];
        #pragma unroll
        for (int e0 = 0; e0 < 4; e0++) {
            float2 o0, o1, o2, o3;
            bfly4(X[e0], X[e0 + 4], X[e0 + 8], X[e0 + 12], o0, o1, o2, o3);
            Y[e0]      = o0;
            Y[4 + e0]  = cmul(o1, wA[e0][0]);
            Y[8 + e0]  = cmul(o2, wA[e0][1]);
            Y[12 + e0] = cmul(o3, wA[e0][2]);
        }

        // -------- Stage B (stride 4) -> warp-private Ex rows -------------
        // slot = 16s + 4r + q (same algebra as R12/R13)
        #pragma unroll
        for (int r = 0; r < 4; r++) {
            float2 o0, o1, o2, o3;
            bfly4(Y[4 * r + 0], Y[4 * r + 1], Y[4 * r + 2], Y[4 * r + 3],
                  o0, o1, o2, o3);
            int base = row * Sd + q;
            Ex[base + 4 * r]      = o0;                 // s=0
            Ex[base + 16 + 4 * r] = cmul(o1, wB[0]);    // s=1
            Ex[base + 32 + 4 * r] = cmul(o2, wB[1]);    // s=2
            Ex[base + 48 + 4 * r] = cmul(o3, wB[2]);    // s=3
        }
        __syncwarp();   // writes visible within the owning warp

        // -------- Stage C (stride 1, r=q) + diag(t) -> back to X ---------
        #pragma unroll
        for (int s = 0; s < 4; s++) {
            int base = row * Sd + 16 * s + 4 * q;
            float2 o0, o1, o2, o3;
            bfly4(Ex[base + 0], Ex[base + 1], Ex[base + 2], Ex[base + 3],
                  o0, o1, o2, o3);
            int nb = 4 * s + q;
            X[s]      = cmul(o0, tSb[nb]);          // tau=0
            X[4 + s]  = cmul(o1, tSb[nb + 16]);     // tau=1
            X[8 + s]  = cmul(o2, tSb[nb + 32]);     // tau=2
            X[12 + s] = cmul(o3, tSb[nb + 48]);     // tau=3
        }
        __syncwarp();   // all reads done before next k's writes (same warp)
    }
    __syncthreads();   // all warps done before smem is repurposed

    // ============ M -> SoA planes (Mre, -Mim), stride 66 floats ===========
    float* shf = (float*)sh;
    float* Xr  = shf;                       // [8192] floats (128x64)
    float* Xi  = shf + 8192;                // [8192] floats
    float* Mre = shf + 17024;               // byte ofs 68096, 4224 floats
    float* Mim = Mre + Nn * 66;             // 4224 floats (pre-negated)

    #pragma unroll
    for (int e = 0; e < 16; e++) {
        int n = q + 4 * e;
        Mre[row * 66 + n] =  X[e].x;
        Mim[row * 66 + n] = -X[e].y;
    }
    __syncthreads();

    // =================== Phase B: apply (real part only) ==================
    const int tb = tid >> 4;            // 0..15 -> batch rows {8tb..8tb+7}
    const int ti = tid & 15;            // output cols {ti,+16,+32,+48}

    for (int bt = 0; bt < Bb / 128; ++bt) {
        for (int idx = tid; idx < 128 * Nn; idx += 256) {
            int r = idx >> 6, j = idx & 63;
            long long b = (long long)bt * 128 + r;
            long long g = ((b * Dd + d) * Ww + w) * Nn + j;
            Xr[r * 64 + j] = gldf(xr, g * xstride, nxr);
            Xi[r * 64 + j] = gldf(xi, g * xstride, nxi);
        }
        __syncthreads();

        u64t acc[8][4];
        #pragma unroll
        for (int r = 0; r < 8; r++)
            #pragma unroll
            for (int c = 0; c < 4; c++)
                acc[r][c] = 0ull;

        for (int jp = 0; jp < Nn / 2; ++jp) {
            u64t mr2[4], mi2[4];
            #pragma unroll
            for (int c = 0; c < 4; c++) {
                mr2[c] = *(const u64t*)(Mre + (ti + 16 * c) * 66 + 2 * jp);
                mi2[c] = *(const u64t*)(Mim + (ti + 16 * c) * 66 + 2 * jp);
            }
            #pragma unroll
            for (int r = 0; r < 8; r++) {
                u64t xr2 = *(const u64t*)(Xr + (tb * 8 + r) * 64 + 2 * jp);
                u64t xi2 = *(const u64t*)(Xi + (tb * 8 + r) * 64 + 2 * jp);
                #pragma unroll
                for (int c = 0; c < 4; c++) {
                    ffma2(acc[r][c], xr2, mr2[c]);
                    ffma2(acc[r][c], xi2, mi2[c]);   // Mim pre-negated
                }
            }
        }

        #pragma unroll
        for (int r = 0; r < 8; r++)
            #pragma unroll
            for (int c = 0; c < 4; c++) {
                float lo = __uint_as_float((unsigned)(acc[r][c] & 0xffffffffu));
                float hi = __uint_as_float((unsigned)(acc[r][c] >> 32));
                float re = lo + hi;
                long long b = (long long)bt * 128 + tb * 8 + r;
                int i = ti + 16 * c;
                long long g = ((b * Dd + d) * Ww + w) * Nn + i;
                if (g < nof) outf[g] = re;
            }
        __syncthreads();
    }
}

// ---------------------------------------------------------------------------
extern "C" void kernel_launch(void* const* d_in, const int* in_sizes, int n_in,
                              void* d_out, int out_size)
{
    const long long NX = (long long)Bb * Dd * Ww * Nn;   // 33,554,432
    const long long NV = (long long)Kk * Dd * Nn;        // 32,768
    const long long NW = Ww;                             // 128

    const float *x0 = 0, *x1 = 0, *vals = 0, *wls = 0;
    long long nx0 = 0, nx1 = 0, nv = 0, nw = 0;
    int xcomplex = 0;

    for (int pass = 0; pass < 2; ++pass) {
        long long mul = (pass == 0) ? 1 : 4;
        x0 = x1 = vals = wls = 0; nx0 = nx1 = nv = nw = 0; xcomplex = 0;
        int nxbuf = 0;
        for (int i = 0; i < n_in; i++) {
            long long s = (long long)in_sizes[i];
            const float* p = (const float*)d_in[i];
            if (!p) continue;
            if (s == NX * mul) {
                if (nxbuf == 0) { x0 = p; nx0 = NX; nxbuf = 1; }
                else if (nxbuf == 1) { x1 = p; nx1 = NX; nxbuf = 2; }
            } else if (s == 2 * NX * mul) {
                x0 = p; nx0 = 2 * NX; nxbuf = 2; xcomplex = 1;
            } else if (s == NV * mul) { if (!vals) { vals = p; nv = NV; } }
            else if (s == NW * mul)   { if (!wls)  { wls  = p; nw = NW; } }
        }
        if (nxbuf == 1 && vals && wls) {
            xcomplex = 1; nx0 = 2 * NX; x1 = 0; nxbuf = 2;
        }
        if (nxbuf == 2 && vals && wls) break;
        x0 = 0;
    }

    if (!(x0 && vals && wls) || !d_out) {
        long long n = (out_size > 4) ? (long long)out_size / 4 : 1;
        pic_probe<<<(unsigned)((n + 255) / 256), 256>>>((float*)d_out, n);
        return;
    }

    // d_out = out_size float32 (real part) — established R8.
    long long n_floats = ((long long)out_size < NX) ? (long long)out_size : NX;

    const float* xrp; const float* xip; long long nxr, nxi; int xstride;
    if (xcomplex) { xrp = x0; nxr = nx0; xip = x0 + 1; nxi = nx0 - 1; xstride = 2; }
    else          { xrp = x0; nxr = nx0; xip = x1;     nxi = nx1;     xstride = 1; }

    cudaFuncSetAttribute(pic_fused, cudaFuncAttributeMaxDynamicSharedMemorySize,
                         SMEM_BYTES);

    dim3 grid(Ww, Dd);
    pic_fused<<<grid, 256, SMEM_BYTES>>>(vals, nv, wls, nw,
                                         xrp, nxr, xip, nxi, xstride,
                                         (float*)d_out, n_floats);
}